// round 4
// baseline (speedup 1.0000x reference)
#include <cuda_runtime.h>
#include <math.h>

#define NN 768

// ---------------- scratch ----------------
__device__ float g_q[64*NN], g_k[64*NN], g_vT[NN*64];
__device__ float g_A[128*NN], g_B[128*NN];
__device__ float2 g_nc1[128];   // stage1 inorm+bnorm composite (scale,bias)
__device__ float2 g_nc2[128];   // stage2
__device__ float2 g_ncc[128];   // cat bnorm1d
__device__ float g_Sq[NN], g_Sk[NN];
__device__ float g_avp[4*64*NN], g_av2[64*NN], g_g1[128*NN];

// ---------------- helpers ----------------
__device__ __forceinline__ float bsum_buf(float v, volatile float* sb) {
    #pragma unroll
    for (int o = 16; o; o >>= 1) v += __shfl_xor_sync(0xffffffffu, v, o);
    if ((threadIdx.x & 31) == 0) sb[threadIdx.x >> 5] = v;
    __syncthreads();
    if (threadIdx.x == 0) {
        float s = sb[0];
        #pragma unroll
        for (int i = 1; i < 8; i++) s += sb[i];
        sb[0] = s;
    }
    __syncthreads();
    return sb[0];
}

// Stage transposed weight tile wT[KK][16]
__device__ __forceinline__ void fill_W16(float* wT, const float* __restrict__ W,
                                         int ldw, int o0, int koff, int KK) {
    for (int v = threadIdx.x; v < KK * 16; v += 256) {
        int i = v >> 4, r = v & 15;
        wT[v] = W[(o0 + r) * ldw + koff + i];
    }
}

// 16 rows x 128 cols, X streamed from global. acc[8].
template<int KK>
__device__ __forceinline__ void gemm16d(const float* __restrict__ X, int c0,
                                        const float* wT, float acc[8]) {
    int c = threadIdx.x & 127, rg = threadIdx.x >> 7;
    const float* xp = X + c0 + c;
    const float* wp = wT + rg * 8;
    #pragma unroll 8
    for (int i = 0; i < KK; i++) {
        float x = __ldg(xp + i * NN);
        float4 w0 = *(const float4*)(wp + i * 16);
        float4 w1 = *(const float4*)(wp + i * 16 + 4);
        acc[0] = fmaf(w0.x, x, acc[0]); acc[1] = fmaf(w0.y, x, acc[1]);
        acc[2] = fmaf(w0.z, x, acc[2]); acc[3] = fmaf(w0.w, x, acc[3]);
        acc[4] = fmaf(w1.x, x, acc[4]); acc[5] = fmaf(w1.y, x, acc[5]);
        acc[6] = fmaf(w1.z, x, acc[6]); acc[7] = fmaf(w1.w, x, acc[7]);
    }
}

// Same, applying relu(nb[i].x * x + nb[i].y) on load (nb in smem).
template<int KK>
__device__ __forceinline__ void gemm16d_norm(const float* __restrict__ X, int c0,
                                             const float* wT, const float2* nb,
                                             float acc[8]) {
    int c = threadIdx.x & 127, rg = threadIdx.x >> 7;
    const float* xp = X + c0 + c;
    const float* wp = wT + rg * 8;
    #pragma unroll 8
    for (int i = 0; i < KK; i++) {
        float2 sb = nb[i];
        float x = fmaxf(fmaf(sb.x, __ldg(xp + i * NN), sb.y), 0.f);
        float4 w0 = *(const float4*)(wp + i * 16);
        float4 w1 = *(const float4*)(wp + i * 16 + 4);
        acc[0] = fmaf(w0.x, x, acc[0]); acc[1] = fmaf(w0.y, x, acc[1]);
        acc[2] = fmaf(w0.z, x, acc[2]); acc[3] = fmaf(w0.w, x, acc[3]);
        acc[4] = fmaf(w1.x, x, acc[4]); acc[5] = fmaf(w1.y, x, acc[5]);
        acc[6] = fmaf(w1.z, x, acc[6]); acc[7] = fmaf(w1.w, x, acc[7]);
    }
}

// Same, X = sum of 4 split-k partials (stride S between them).
template<int KK, int S>
__device__ __forceinline__ void gemm16d_s4(const float* __restrict__ X, int c0,
                                           const float* wT, float acc[8]) {
    int c = threadIdx.x & 127, rg = threadIdx.x >> 7;
    const float* xp = X + c0 + c;
    const float* wp = wT + rg * 8;
    #pragma unroll 4
    for (int i = 0; i < KK; i++) {
        float x0 = __ldg(xp + i * NN);
        float x1 = __ldg(xp + i * NN + S);
        float x2 = __ldg(xp + i * NN + 2 * S);
        float x3 = __ldg(xp + i * NN + 3 * S);
        float x = (x0 + x1) + (x2 + x3);
        float4 w0 = *(const float4*)(wp + i * 16);
        float4 w1 = *(const float4*)(wp + i * 16 + 4);
        acc[0] = fmaf(w0.x, x, acc[0]); acc[1] = fmaf(w0.y, x, acc[1]);
        acc[2] = fmaf(w0.z, x, acc[2]); acc[3] = fmaf(w0.w, x, acc[3]);
        acc[4] = fmaf(w1.x, x, acc[4]); acc[5] = fmaf(w1.y, x, acc[5]);
        acc[6] = fmaf(w1.z, x, acc[6]); acc[7] = fmaf(w1.w, x, acc[7]);
    }
}

// ---------------- kernels ----------------

// q,k,v convs (v written transposed). Grid 72 x 256.
__global__ void k_qkv(const float* __restrict__ d1, const float* __restrict__ d2,
                      const float* __restrict__ qw, const float* __restrict__ qb,
                      const float* __restrict__ kw, const float* __restrict__ kb,
                      const float* __restrict__ vw, const float* __restrict__ vb)
{
    __shared__ float wT[64 * 16];
    int b = blockIdx.x;
    int grp = b / 24, lb = b % 24;
    int rowblk = lb / 6, colblk = lb % 6;
    int o0 = rowblk * 16, c0 = colblk * 128;
    const float *W, *X, *Bb;
    if (grp == 0)      { W = qw; X = d1; Bb = qb; }
    else if (grp == 1) { W = kw; X = d2; Bb = kb; }
    else               { W = vw; X = d2; Bb = vb; }
    fill_W16(wT, W, 64, o0, 0, 64);
    __syncthreads();
    float acc[8] = {};
    gemm16d<64>(X, c0, wT, acc);
    int c = threadIdx.x & 127, rg = threadIdx.x >> 7;
    int obase = o0 + rg * 8;
    if (grp < 2) {
        float* Y = (grp == 0) ? g_q : g_k;
        #pragma unroll
        for (int r = 0; r < 8; r++)
            Y[(obase + r) * NN + c0 + c] = acc[r] + Bb[obase + r];
    } else {
        int n = c0 + c;
        float4 v0, v1;
        v0.x = acc[0] + Bb[obase + 0]; v0.y = acc[1] + Bb[obase + 1];
        v0.z = acc[2] + Bb[obase + 2]; v0.w = acc[3] + Bb[obase + 3];
        v1.x = acc[4] + Bb[obase + 4]; v1.y = acc[5] + Bb[obase + 5];
        v1.z = acc[6] + Bb[obase + 6]; v1.w = acc[7] + Bb[obase + 7];
        *(float4*)&g_vT[n * 64 + obase]     = v0;
        *(float4*)&g_vT[n * 64 + obase + 4] = v1;
    }
}

// blocks 0..127: stage-1 norm coefficients.  blocks 128..139: Sq/Sk shot rows.
__global__ void k_stats1(const float* __restrict__ bn1g, const float* __restrict__ bn1b,
                         const float* __restrict__ shw)
{
    int b = blockIdx.x;
    int tid = threadIdx.x;
    if (b < 128) {
        const float* src = (b < 64) ? (g_q + b * NN) : (g_k + (b - 64) * NN);
        float s = 0.f, s2 = 0.f;
        #pragma unroll
        for (int j = 0; j < 3; j++) {
            float x = src[tid + j * 256];
            s += x; s2 += x * x;
        }
        __shared__ float r1[8], r2[8];
        s  = bsum_buf(s,  r1);
        s2 = bsum_buf(s2, r2);
        if (tid == 0) {
            float m = s * (1.f / NN);
            float v = s2 * (1.f / NN) - m * m;
            float si = rsqrtf(v + 1e-3f);
            float vb = v * si * si;
            float sb = rsqrtf(vb + 1e-5f);
            float scale = si * sb * bn1g[b];
            g_nc1[b] = make_float2(scale, -m * scale + bn1b[b]);
        }
    } else {
        // Sq[n] = sum_c shw[c]*q[c,n]  (or Sk from k with shw[64:])
        int j = b - 128;
        int half = j / 6, cb = j % 6;
        int n = cb * 128 + (tid & 127);
        int ch = tid >> 7;
        const float* src = half ? g_k : g_q;
        const float* w = shw + half * 64 + ch * 32;
        const float* xp = src + ch * 32 * NN + n;
        float s = 0.f;
        #pragma unroll 8
        for (int i = 0; i < 32; i++) s = fmaf(w[i], __ldg(xp + i * NN), s);
        __shared__ float red[256];
        red[tid] = s;
        __syncthreads();
        if (tid < 128) {
            float* dst = half ? g_Sk : g_Sq;
            dst[n] = red[tid] + red[tid + 128];
        }
    }
}

// A = w1[:,:64] @ relu(norm(q));  B = w1[:,64:] @ relu(norm(k)) + b1. Grid 96 x 256.
__global__ void k_AB(const float* __restrict__ w1, const float* __restrict__ b1)
{
    __shared__ float wT[64 * 16];
    __shared__ float2 nb[64];
    int b = blockIdx.x;
    int half = b / 48, lb = b % 48;
    int rowblk = lb / 6, colblk = lb % 6;
    int o0 = rowblk * 16, c0 = colblk * 128;
    const float* X = half ? g_k : g_q;
    if (threadIdx.x < 64) nb[threadIdx.x] = g_nc1[half * 64 + threadIdx.x];
    fill_W16(wT, w1, 128, o0, half ? 64 : 0, 64);
    __syncthreads();
    float acc[8] = {};
    gemm16d_norm<64>(X, c0, wT, nb, acc);
    int c = threadIdx.x & 127, rg = threadIdx.x >> 7;
    int obase = o0 + rg * 8;
    if (half == 0) {
        #pragma unroll
        for (int r = 0; r < 8; r++)
            g_A[(obase + r) * NN + c0 + c] = acc[r];
    } else {
        #pragma unroll
        for (int r = 0; r < 8; r++)
            g_B[(obase + r) * NN + c0 + c] = acc[r] + b1[obase + r];
    }
}

// Stage-2 composite norm coefficients from separable stats. 128 x 256.
__global__ void k_stats2(const float* __restrict__ bn2g, const float* __restrict__ bn2b)
{
    int o = blockIdx.x;
    int tid = threadIdx.x;
    float sA = 0.f, qA = 0.f, sB = 0.f, qB = 0.f;
    #pragma unroll
    for (int j = 0; j < 3; j++) {
        float a = g_A[o * NN + tid + j * 256];
        float b = g_B[o * NN + tid + j * 256];
        sA += a; qA += a * a; sB += b; qB += b * b;
    }
    __shared__ float r1[8], r2[8], r3[8], r4[8];
    sA = bsum_buf(sA, r1); qA = bsum_buf(qA, r2);
    sB = bsum_buf(sB, r3); qB = bsum_buf(qB, r4);
    if (tid == 0) {
        float mA = sA * (1.f / NN), mB = sB * (1.f / NN);
        float vA = qA * (1.f / NN) - mA * mA;
        float vB = qB * (1.f / NN) - mB * mB;
        float m2 = mA + mB, v2 = vA + vB;
        float si = rsqrtf(v2 + 1e-3f);
        float vb = v2 * si * si;
        float sb = rsqrtf(vb + 1e-5f);
        float scale = si * sb * bn2g[o];
        g_nc2[o] = make_float2(scale, -m2 * scale + bn2b[o]);
    }
}

// score_pre[n,m] = sum_o w2[o]*relu(At[o,n]+Bt[o,m]) + cc + Sq[n] + Sk[m]
// 64x64 tiles, 512 threads, o-chunked by 64. Grid (12,12).
__global__ void __launch_bounds__(512)
k_score(const float* __restrict__ w2, const float* __restrict__ b2p,
        const float* __restrict__ bsp, float* __restrict__ out)
{
    __shared__ float As[64 * 64];
    __shared__ float Bs[64 * 64];
    __shared__ float2 scb[128];
    __shared__ float w2s[128];
    __shared__ float Sqs[64], Sks[64];
    int tid = threadIdx.x;
    int n0 = blockIdx.y * 64, m0 = blockIdx.x * 64;
    if (tid < 128) { scb[tid] = g_nc2[tid]; w2s[tid] = w2[tid]; }
    else if (tid < 192) Sqs[tid - 128] = g_Sq[n0 + tid - 128];
    else if (tid < 256) Sks[tid - 192] = g_Sk[m0 + tid - 192];
    __syncthreads();

    int tx = tid & 15;        // m: 4-wide
    int ty = tid >> 4;        // n: 2-wide (0..31)
    float acc[2][4] = {};
    #pragma unroll
    for (int ch = 0; ch < 2; ch++) {
        #pragma unroll
        for (int v = tid; v < 1024; v += 512) {
            int o = v >> 4, t4 = (v & 15) << 2;
            int og = ch * 64 + o;
            float2 sb = scb[og];
            float4 a = *(const float4*)&g_A[og * NN + n0 + t4];
            a.x = fmaf(sb.x, a.x, sb.y); a.y = fmaf(sb.x, a.y, sb.y);
            a.z = fmaf(sb.x, a.z, sb.y); a.w = fmaf(sb.x, a.w, sb.y);
            *(float4*)&As[o * 64 + t4] = a;
        }
        #pragma unroll
        for (int v = tid; v < 1024; v += 512) {
            int o = v >> 4, t4 = (v & 15) << 2;
            int og = ch * 64 + o;
            float s = scb[og].x;
            float4 bv = *(const float4*)&g_B[og * NN + m0 + t4];
            bv.x *= s; bv.y *= s; bv.z *= s; bv.w *= s;
            *(float4*)&Bs[o * 64 + t4] = bv;
        }
        __syncthreads();
        #pragma unroll 4
        for (int o = 0; o < 64; o++) {
            float2 a = *(const float2*)&As[o * 64 + ty * 2];
            float4 bv = *(const float4*)&Bs[o * 64 + tx * 4];
            float w = w2s[ch * 64 + o];
            acc[0][0] = fmaf(w, fmaxf(a.x + bv.x, 0.f), acc[0][0]);
            acc[0][1] = fmaf(w, fmaxf(a.x + bv.y, 0.f), acc[0][1]);
            acc[0][2] = fmaf(w, fmaxf(a.x + bv.z, 0.f), acc[0][2]);
            acc[0][3] = fmaf(w, fmaxf(a.x + bv.w, 0.f), acc[0][3]);
            acc[1][0] = fmaf(w, fmaxf(a.y + bv.x, 0.f), acc[1][0]);
            acc[1][1] = fmaf(w, fmaxf(a.y + bv.y, 0.f), acc[1][1]);
            acc[1][2] = fmaf(w, fmaxf(a.y + bv.z, 0.f), acc[1][2]);
            acc[1][3] = fmaf(w, fmaxf(a.y + bv.w, 0.f), acc[1][3]);
        }
        __syncthreads();
    }
    float cc = __ldg(b2p) + __ldg(bsp);
    #pragma unroll
    for (int rn = 0; rn < 2; rn++) {
        int n = n0 + ty * 2 + rn;
        float sq = Sqs[ty * 2 + rn] + cc;
        float4 o4;
        o4.x = acc[rn][0] + sq + Sks[tx * 4 + 0];
        o4.y = acc[rn][1] + sq + Sks[tx * 4 + 1];
        o4.z = acc[rn][2] + sq + Sks[tx * 4 + 2];
        o4.w = acc[rn][3] + sq + Sks[tx * 4 + 3];
        *(float4*)&out[n * NN + m0 + tx * 4] = o4;
    }
}

// warp-per-row softmax, in place. 96 x 256.
__global__ void k_softmax(float* __restrict__ score)
{
    int row = blockIdx.x * 8 + (threadIdx.x >> 5);
    int lane = threadIdx.x & 31;
    float* p = score + row * NN;
    float v[24];
    float mx = -1e30f;
    #pragma unroll
    for (int i = 0; i < 24; i++) { v[i] = p[lane + i * 32]; mx = fmaxf(mx, v[i]); }
    #pragma unroll
    for (int o = 16; o; o >>= 1) mx = fmaxf(mx, __shfl_xor_sync(0xffffffffu, mx, o));
    float s = 0.f;
    #pragma unroll
    for (int i = 0; i < 24; i++) { v[i] = __expf(v[i] - mx); s += v[i]; }
    #pragma unroll
    for (int o = 16; o; o >>= 1) s += __shfl_xor_sync(0xffffffffu, s, o);
    float inv = 1.f / s;
    #pragma unroll
    for (int i = 0; i < 24; i++) p[lane + i * 32] = v[i] * inv;
}

// av partials: 48 n-tiles x 4 k-splits = 192 x 256.
__global__ void k_av(const float* __restrict__ score)
{
    int bx = blockIdx.x;
    int nt = bx % 48, ks = bx / 48;
    int n0 = nt * 16;
    int tid = threadIdx.x;
    __shared__ float Vs[64][64];
    __shared__ float Ps[16][64];
    int d0  = (tid & 31) * 2;
    int nl0 = (tid >> 5) * 2;
    float a00 = 0.f, a01 = 0.f, a10 = 0.f, a11 = 0.f;
    for (int c = 0; c < 3; c++) {
        int mb = ks * 192 + c * 64;
        for (int idx = tid; idx < 64 * 64; idx += 256)
            Vs[idx >> 6][idx & 63] = g_vT[(mb + (idx >> 6)) * 64 + (idx & 63)];
        for (int idx = tid; idx < 16 * 64; idx += 256)
            Ps[idx >> 6][idx & 63] = score[(n0 + (idx >> 6)) * NN + mb + (idx & 63)];
        __syncthreads();
        #pragma unroll 4
        for (int m = 0; m < 64; m++) {
            float2 vv = *(const float2*)&Vs[m][d0];
            float p0 = Ps[nl0][m], p1 = Ps[nl0 + 1][m];
            a00 = fmaf(p0, vv.x, a00); a01 = fmaf(p0, vv.y, a01);
            a10 = fmaf(p1, vv.x, a10); a11 = fmaf(p1, vv.y, a11);
        }
        __syncthreads();
    }
    float* dst = g_avp + ks * (64 * NN);
    dst[d0 * NN + n0 + nl0]           = a00;
    dst[(d0 + 1) * NN + n0 + nl0]     = a01;
    dst[d0 * NN + n0 + nl0 + 1]       = a10;
    dst[(d0 + 1) * NN + n0 + nl0 + 1] = a11;
}

// mh conv, summing the 4 split-k partials on load. Grid 24 x 256.
__global__ void k_mh(const float* __restrict__ mhw, const float* __restrict__ mhb)
{
    __shared__ float wT[64 * 16];
    int lb = blockIdx.x;
    int rowblk = lb / 6, colblk = lb % 6;
    int o0 = rowblk * 16, c0 = colblk * 128;
    fill_W16(wT, mhw, 64, o0, 0, 64);
    __syncthreads();
    float acc[8] = {};
    gemm16d_s4<64, 64 * NN>(g_avp, c0, wT, acc);
    int c = threadIdx.x & 127, rg = threadIdx.x >> 7;
    int obase = o0 + rg * 8;
    #pragma unroll
    for (int r = 0; r < 8; r++)
        g_av2[(obase + r) * NN + c0 + c] = acc[r] + mhb[obase + r];
}

// g1 = cat_w1 @ [desc1; av2] + cat_b1. Grid 48 x 256.
__global__ void k_cat1(const float* __restrict__ w1, const float* __restrict__ desc1,
                       const float* __restrict__ b1)
{
    __shared__ float wT[64 * 16];
    int lb = blockIdx.x;
    int rowblk = lb / 6, colblk = lb % 6;
    int o0 = rowblk * 16, c0 = colblk * 128;
    float acc[8] = {};
    fill_W16(wT, w1, 128, o0, 0, 64);
    __syncthreads();
    gemm16d<64>(desc1, c0, wT, acc);
    __syncthreads();
    fill_W16(wT, w1, 128, o0, 64, 64);
    __syncthreads();
    gemm16d<64>(g_av2, c0, wT, acc);
    int c = threadIdx.x & 127, rg = threadIdx.x >> 7;
    int obase = o0 + rg * 8;
    #pragma unroll
    for (int r = 0; r < 8; r++)
        g_g1[(obase + r) * NN + c0 + c] = acc[r] + b1[obase + r];
}

// bnorm1d stats only -> coeffs. 128 x 256.
__global__ void k_bnstats(const float* __restrict__ cbg, const float* __restrict__ cbb)
{
    int o = blockIdx.x;
    int tid = threadIdx.x;
    float s = 0.f, s2 = 0.f;
    #pragma unroll
    for (int j = 0; j < 3; j++) {
        float x = g_g1[o * NN + tid + j * 256];
        s += x; s2 += x * x;
    }
    __shared__ float r1[8], r2[8];
    s = bsum_buf(s, r1); s2 = bsum_buf(s2, r2);
    if (tid == 0) {
        float m = s * (1.f / NN);
        float v = s2 * (1.f / NN) - m * m;
        float scale = rsqrtf(v + 1e-5f) * cbg[o];
        g_ncc[o] = make_float2(scale, -m * scale + cbb[o]);
    }
}

// out_desc = desc1 + cat_w2 @ relu(norm(g1)) + cat_b2. Grid 24 x 256.
__global__ void k_final(const float* __restrict__ cw2, const float* __restrict__ cb2,
                        const float* __restrict__ desc1, float* __restrict__ out)
{
    __shared__ float wT[64 * 16];
    __shared__ float2 nb[64];
    int lb = blockIdx.x;
    int rowblk = lb / 6, colblk = lb % 6;
    int o0 = rowblk * 16, c0 = colblk * 128;
    float acc[8] = {};
    if (threadIdx.x < 64) nb[threadIdx.x] = g_ncc[threadIdx.x];
    fill_W16(wT, cw2, 128, o0, 0, 64);
    __syncthreads();
    gemm16d_norm<64>(g_g1, c0, wT, nb, acc);
    __syncthreads();
    if (threadIdx.x < 64) nb[threadIdx.x] = g_ncc[64 + threadIdx.x];
    fill_W16(wT, cw2, 128, o0, 64, 64);
    __syncthreads();
    gemm16d_norm<64>(g_g1 + 64 * NN, c0, wT, nb, acc);
    int c = threadIdx.x & 127, rg = threadIdx.x >> 7;
    int obase = o0 + rg * 8;
    #pragma unroll
    for (int r = 0; r < 8; r++)
        out[(obase + r) * NN + c0 + c] =
            acc[r] + cb2[obase + r] + desc1[(obase + r) * NN + c0 + c];
}

// ---------------- launch ----------------
extern "C" void kernel_launch(void* const* d_in, const int* in_sizes, int n_in,
                              void* d_out, int out_size)
{
    const float* desc1 = (const float*)d_in[0];
    const float* desc2 = (const float*)d_in[1];
    const float* qw  = (const float*)d_in[2];  const float* qb  = (const float*)d_in[3];
    const float* kw  = (const float*)d_in[4];  const float* kb  = (const float*)d_in[5];
    const float* vw  = (const float*)d_in[6];  const float* vb  = (const float*)d_in[7];
    const float* mhw = (const float*)d_in[8];  const float* mhb = (const float*)d_in[9];
    const float* cw1 = (const float*)d_in[10]; const float* cb1 = (const float*)d_in[11];
    const float* cbg = (const float*)d_in[12]; const float* cbb = (const float*)d_in[13];
    const float* cw2 = (const float*)d_in[14]; const float* cb2 = (const float*)d_in[15];
    const float* shw = (const float*)d_in[16]; const float* shb = (const float*)d_in[17];
    const float* bn1g = (const float*)d_in[18]; const float* bn1b = (const float*)d_in[19];
    const float* sw1 = (const float*)d_in[20]; const float* sb1 = (const float*)d_in[21];
    const float* bn2g = (const float*)d_in[22]; const float* bn2b = (const float*)d_in[23];
    const float* sw2 = (const float*)d_in[24]; const float* sb2 = (const float*)d_in[25];

    float* out = (float*)d_out;
    float* out_desc  = out;
    float* out_score = out + 64 * NN;

    k_qkv<<<72, 256>>>(desc1, desc2, qw, qb, kw, kb, vw, vb);
    k_stats1<<<140, 256>>>(bn1g, bn1b, shw);
    k_AB<<<96, 256>>>(sw1, sb1);
    k_stats2<<<128, 256>>>(bn2g, bn2b);
    k_score<<<dim3(12, 12), 512>>>(sw2, sb2, shb, out_score);
    k_softmax<<<96, 256>>>(out_score);
    k_av<<<192, 256>>>(out_score);
    k_mh<<<24, 256>>>(mhw, mhb);
    k_cat1<<<48, 256>>>(cw1, desc1, cb1);
    k_bnstats<<<128, 256>>>(cbg, cbb);
    k_final<<<24, 256>>>(cw2, cb2, desc1, out_desc);
}

// round 5
// speedup vs baseline: 1.1428x; 1.1428x over previous
#include <cuda_runtime.h>
#include <math.h>

#define NN 768

// ---------------- scratch ----------------
__device__ float g_q[64*NN], g_k[64*NN], g_vT[NN*64];
__device__ float g_A[128*NN], g_B[128*NN];
__device__ float2 g_nc1[128], g_nc2[128], g_ncc[128];
__device__ float g_Sq[NN], g_Sk[NN];
__device__ float g_avp[4*64*NN], g_g1[128*NN];
__device__ float g_Wp[128*64], g_bp[128];
__device__ int g_bar_count;
__device__ volatile int g_bar_gen;

// ---------------- grid barrier (all 512 blocks co-resident) ----------------
__device__ __forceinline__ void gsync() {
    __threadfence();
    __syncthreads();
    if (threadIdx.x == 0) {
        int gen = g_bar_gen;
        if (atomicAdd(&g_bar_count, 1) == (int)gridDim.x - 1) {
            g_bar_count = 0;
            __threadfence();
            g_bar_gen = gen + 1;
        } else {
            while (g_bar_gen == gen) __nanosleep(64);
        }
        __threadfence();
    }
    __syncthreads();
}

// ---------------- helpers ----------------
__device__ __forceinline__ float bsum256(float v, volatile float* sb) {
    #pragma unroll
    for (int o = 16; o; o >>= 1) v += __shfl_xor_sync(0xffffffffu, v, o);
    if ((threadIdx.x & 31) == 0) sb[threadIdx.x >> 5] = v;
    __syncthreads();
    if (threadIdx.x == 0) {
        float s = sb[0];
        #pragma unroll
        for (int i = 1; i < 8; i++) s += sb[i];
        sb[0] = s;
    }
    __syncthreads();
    return sb[0];
}

// wT[i*8+r] = W[(o0+r)*ldw + koff + i], i<64, r<8
__device__ __forceinline__ void fillW8(float* wT, const float* __restrict__ W,
                                       int ldw, int o0, int koff) {
    #pragma unroll
    for (int v = threadIdx.x; v < 512; v += 256) {
        int i = v >> 3, r = v & 7;
        wT[v] = W[(o0 + r) * ldw + koff + i];
    }
}

// 8 rows x 128 cols tile, K=64; 256 thr = 128 cols x 2 row-groups (4 rows each)
__device__ __forceinline__ void gemm8p(const float* __restrict__ X, int c0,
                                       const float* wT, float acc[4]) {
    int c = threadIdx.x & 127, rg = threadIdx.x >> 7;
    const float* xp = X + c0 + c;
    const float* wp = wT + rg * 4;
    #pragma unroll 8
    for (int i = 0; i < 64; i++) {
        float x = __ldg(xp + i * NN);
        float4 w = *(const float4*)(wp + i * 8);
        acc[0] = fmaf(w.x, x, acc[0]); acc[1] = fmaf(w.y, x, acc[1]);
        acc[2] = fmaf(w.z, x, acc[2]); acc[3] = fmaf(w.w, x, acc[3]);
    }
}

__device__ __forceinline__ void gemm8n(const float* __restrict__ X, int c0,
                                       const float* wT, const float2* nb,
                                       float acc[4]) {
    int c = threadIdx.x & 127, rg = threadIdx.x >> 7;
    const float* xp = X + c0 + c;
    const float* wp = wT + rg * 4;
    #pragma unroll 8
    for (int i = 0; i < 64; i++) {
        float2 sb = nb[i];
        float x = fmaxf(fmaf(sb.x, __ldg(xp + i * NN), sb.y), 0.f);
        float4 w = *(const float4*)(wp + i * 8);
        acc[0] = fmaf(w.x, x, acc[0]); acc[1] = fmaf(w.y, x, acc[1]);
        acc[2] = fmaf(w.z, x, acc[2]); acc[3] = fmaf(w.w, x, acc[3]);
    }
}

// X = sum of 4 split-k partials at stride S
__device__ __forceinline__ void gemm8s4(const float* __restrict__ X, int c0,
                                        const float* wT, float acc[4]) {
    const int S = 64 * NN;
    int c = threadIdx.x & 127, rg = threadIdx.x >> 7;
    const float* xp = X + c0 + c;
    const float* wp = wT + rg * 4;
    #pragma unroll 4
    for (int i = 0; i < 64; i++) {
        float x = (__ldg(xp + i * NN) + __ldg(xp + i * NN + S)) +
                  (__ldg(xp + i * NN + 2 * S) + __ldg(xp + i * NN + 3 * S));
        float4 w = *(const float4*)(wp + i * 8);
        acc[0] = fmaf(w.x, x, acc[0]); acc[1] = fmaf(w.y, x, acc[1]);
        acc[2] = fmaf(w.z, x, acc[2]); acc[3] = fmaf(w.w, x, acc[3]);
    }
}

// ---------------- the single fused kernel ----------------
__global__ void __launch_bounds__(256, 4)
k_fused(const float* __restrict__ desc1, const float* __restrict__ desc2,
        const float* __restrict__ qw, const float* __restrict__ qb,
        const float* __restrict__ kw, const float* __restrict__ kb,
        const float* __restrict__ vw, const float* __restrict__ vbias,
        const float* __restrict__ mhw, const float* __restrict__ mhb,
        const float* __restrict__ cw1, const float* __restrict__ cb1,
        const float* __restrict__ cbg, const float* __restrict__ cbb,
        const float* __restrict__ cw2, const float* __restrict__ cb2,
        const float* __restrict__ shw, const float* __restrict__ shb,
        const float* __restrict__ bn1g, const float* __restrict__ bn1b,
        const float* __restrict__ sw1, const float* __restrict__ sb1,
        const float* __restrict__ bn2g, const float* __restrict__ bn2b,
        const float* __restrict__ sw2, const float* __restrict__ sb2,
        float* __restrict__ out_desc, float* __restrict__ out_score)
{
    __shared__ union {
        struct { float wT[512]; float2 nb[64]; } g;
        struct { float red[256]; float r1[8]; float r2[8]; float r3[8]; float r4[8]; } st;
        struct { float As[64*32]; float Bs[64*64]; float2 scb[128]; float w2s[128];
                 float Sqs[32]; float Sks[64]; } sc;
        struct { float Vs[64*64]; float Ps[16*64]; } av;
    } sm;

    int vb = blockIdx.x;
    int tid = threadIdx.x;

    // ===== S1: q/k/v convs (v transposed) + fused W' = cw1[:,64:]@mhw, b' =====
    if (vb < 144) {
        int mat = vb / 48, t = vb % 48;
        int o0 = (t / 6) * 8, c0 = (t % 6) * 128;
        const float *W, *X, *Bb;
        if (mat == 0)      { W = qw; X = desc1; Bb = qb; }
        else if (mat == 1) { W = kw; X = desc2; Bb = kb; }
        else               { W = vw; X = desc2; Bb = vbias; }
        fillW8(sm.g.wT, W, 64, o0, 0);
        __syncthreads();
        float acc[4] = {};
        gemm8p(X, c0, sm.g.wT, acc);
        int c = tid & 127, rg = tid >> 7;
        int ob = o0 + rg * 4;
        if (mat < 2) {
            float* Y = (mat == 0) ? g_q : g_k;
            #pragma unroll
            for (int r = 0; r < 4; r++)
                Y[(ob + r) * NN + c0 + c] = acc[r] + Bb[ob + r];
        } else {
            float4 vv;
            vv.x = acc[0] + Bb[ob + 0]; vv.y = acc[1] + Bb[ob + 1];
            vv.z = acc[2] + Bb[ob + 2]; vv.w = acc[3] + Bb[ob + 3];
            *(float4*)&g_vT[(c0 + c) * 64 + ob] = vv;
        }
    } else if (vb < 160) {
        // W'[o,d] = sum_c cw1[o,64+c]*mhw[c,d]; tile 8 o-rows x 64 d
        int o0 = (vb - 144) * 8;
        fillW8(sm.g.wT, cw1, 128, o0, 64);
        __syncthreads();
        int d = tid & 63, rg = tid >> 6;          // 4 groups x 2 rows
        const float* wp = sm.g.wT + rg * 2;
        float a0 = 0.f, a1 = 0.f;
        #pragma unroll 8
        for (int i = 0; i < 64; i++) {
            float x = __ldg(mhw + i * 64 + d);
            float2 w = *(const float2*)(wp + i * 8);
            a0 = fmaf(w.x, x, a0); a1 = fmaf(w.y, x, a1);
        }
        int ob = o0 + rg * 2;
        g_Wp[ob * 64 + d] = a0;
        g_Wp[(ob + 1) * 64 + d] = a1;
    } else if (vb == 160) {
        if (tid < 128) {
            float s = cb1[tid];
            #pragma unroll 8
            for (int i = 0; i < 64; i++)
                s = fmaf(__ldg(cw1 + tid * 128 + 64 + i), __ldg(mhb + i), s);
            g_bp[tid] = s;
        }
    }
    gsync();

    // ===== S2: stage-1 norm coefficients + Sq/Sk shot rows =====
    if (vb < 128) {
        const float* src = (vb < 64) ? (g_q + vb * NN) : (g_k + (vb - 64) * NN);
        float s = 0.f, s2 = 0.f;
        #pragma unroll
        for (int j = 0; j < 3; j++) {
            float x = src[tid + j * 256];
            s += x; s2 += x * x;
        }
        s  = bsum256(s,  sm.st.r1);
        s2 = bsum256(s2, sm.st.r2);
        if (tid == 0) {
            float m = s * (1.f / NN);
            float v = s2 * (1.f / NN) - m * m;
            float si = rsqrtf(v + 1e-3f);
            float vn = v * si * si;
            float sb = rsqrtf(vn + 1e-5f);
            float scale = si * sb * bn1g[vb];
            g_nc1[vb] = make_float2(scale, -m * scale + bn1b[vb]);
        }
    } else if (vb < 140) {
        int j = vb - 128;
        int half = j / 6, cb = j % 6;
        int n = cb * 128 + (tid & 127);
        int ch = tid >> 7;
        const float* src = half ? g_k : g_q;
        const float* w = shw + half * 64 + ch * 32;
        const float* xp = src + ch * 32 * NN + n;
        float s = 0.f;
        #pragma unroll 8
        for (int i = 0; i < 32; i++) s = fmaf(__ldg(w + i), __ldg(xp + i * NN), s);
        sm.st.red[tid] = s;
        __syncthreads();
        if (tid < 128) {
            float* dst = half ? g_Sk : g_Sq;
            dst[n] = sm.st.red[tid] + sm.st.red[tid + 128];
        }
    }
    gsync();

    // ===== S3: A = sw1[:,:64]@relu(norm q); B = sw1[:,64:]@relu(norm k)+sb1 =====
    if (vb < 192) {
        int half = vb / 96, t = vb % 96;
        int o0 = (t / 6) * 8, c0 = (t % 6) * 128;
        if (tid < 64) sm.g.nb[tid] = g_nc1[half * 64 + tid];
        fillW8(sm.g.wT, sw1, 128, o0, half * 64);
        __syncthreads();
        float acc[4] = {};
        gemm8n(half ? g_k : g_q, c0, sm.g.wT, sm.g.nb, acc);
        int c = tid & 127, rg = tid >> 7;
        int ob = o0 + rg * 4;
        if (half == 0) {
            #pragma unroll
            for (int r = 0; r < 4; r++)
                g_A[(ob + r) * NN + c0 + c] = acc[r];
        } else {
            #pragma unroll
            for (int r = 0; r < 4; r++)
                g_B[(ob + r) * NN + c0 + c] = acc[r] + sb1[ob + r];
        }
    }
    gsync();

    // ===== S4: stage-2 norm coefficients (separable stats) =====
    if (vb < 128) {
        float sA = 0.f, qA = 0.f, sB = 0.f, qB = 0.f;
        #pragma unroll
        for (int j = 0; j < 3; j++) {
            float a = g_A[vb * NN + tid + j * 256];
            float b = g_B[vb * NN + tid + j * 256];
            sA += a; qA += a * a; sB += b; qB += b * b;
        }
        sA = bsum256(sA, sm.st.r1); qA = bsum256(qA, sm.st.r2);
        sB = bsum256(sB, sm.st.r3); qB = bsum256(qB, sm.st.r4);
        if (tid == 0) {
            float mA = sA * (1.f / NN), mB = sB * (1.f / NN);
            float vA = qA * (1.f / NN) - mA * mA;
            float vB = qB * (1.f / NN) - mB * mB;
            float m2 = mA + mB, v2 = vA + vB;
            float si = rsqrtf(v2 + 1e-3f);
            float vn = v2 * si * si;
            float sb = rsqrtf(vn + 1e-5f);
            float scale = si * sb * bn2g[vb];
            g_nc2[vb] = make_float2(scale, -m2 * scale + bn2b[vb]);
        }
    }
    gsync();

    // ===== S5: score_pre, 32(n)x64(m) tiles, 288 tiles =====
    if (vb < 288) {
        int n0 = (vb / 12) * 32, m0 = (vb % 12) * 64;
        if (tid < 128) { sm.sc.scb[tid] = g_nc2[tid]; sm.sc.w2s[tid] = sw2[tid]; }
        else if (tid < 160) sm.sc.Sqs[tid - 128] = g_Sq[n0 + tid - 128];
        else if (tid < 224) sm.sc.Sks[tid - 160] = g_Sk[m0 + tid - 160];
        __syncthreads();

        int tx = tid & 15;    // m 4-wide
        int ty = tid >> 4;    // n 2-wide
        float acc[2][4] = {};
        #pragma unroll
        for (int ch = 0; ch < 2; ch++) {
            #pragma unroll
            for (int v = tid; v < 512; v += 256) {
                int o = v >> 3, j4 = (v & 7) << 2;
                int og = ch * 64 + o;
                float2 sb = sm.sc.scb[og];
                float4 a = *(const float4*)&g_A[og * NN + n0 + j4];
                a.x = fmaf(sb.x, a.x, sb.y); a.y = fmaf(sb.x, a.y, sb.y);
                a.z = fmaf(sb.x, a.z, sb.y); a.w = fmaf(sb.x, a.w, sb.y);
                *(float4*)&sm.sc.As[o * 32 + j4] = a;
            }
            #pragma unroll
            for (int v = tid; v < 1024; v += 256) {
                int o = v >> 4, j4 = (v & 15) << 2;
                int og = ch * 64 + o;
                float s = sm.sc.scb[og].x;
                float4 bv = *(const float4*)&g_B[og * NN + m0 + j4];
                bv.x *= s; bv.y *= s; bv.z *= s; bv.w *= s;
                *(float4*)&sm.sc.Bs[o * 64 + j4] = bv;
            }
            __syncthreads();
            #pragma unroll 4
            for (int o = 0; o < 64; o++) {
                float2 a = *(const float2*)&sm.sc.As[o * 32 + ty * 2];
                float4 bv = *(const float4*)&sm.sc.Bs[o * 64 + tx * 4];
                float w = sm.sc.w2s[ch * 64 + o];
                acc[0][0] = fmaf(w, fmaxf(a.x + bv.x, 0.f), acc[0][0]);
                acc[0][1] = fmaf(w, fmaxf(a.x + bv.y, 0.f), acc[0][1]);
                acc[0][2] = fmaf(w, fmaxf(a.x + bv.z, 0.f), acc[0][2]);
                acc[0][3] = fmaf(w, fmaxf(a.x + bv.w, 0.f), acc[0][3]);
                acc[1][0] = fmaf(w, fmaxf(a.y + bv.x, 0.f), acc[1][0]);
                acc[1][1] = fmaf(w, fmaxf(a.y + bv.y, 0.f), acc[1][1]);
                acc[1][2] = fmaf(w, fmaxf(a.y + bv.z, 0.f), acc[1][2]);
                acc[1][3] = fmaf(w, fmaxf(a.y + bv.w, 0.f), acc[1][3]);
            }
            __syncthreads();
        }
        float cc = __ldg(sb2) + __ldg(shb);
        #pragma unroll
        for (int rn = 0; rn < 2; rn++) {
            int n = n0 + ty * 2 + rn;
            float sq = sm.sc.Sqs[ty * 2 + rn] + cc;
            float4 o4;
            o4.x = acc[rn][0] + sq + sm.sc.Sks[tx * 4 + 0];
            o4.y = acc[rn][1] + sq + sm.sc.Sks[tx * 4 + 1];
            o4.z = acc[rn][2] + sq + sm.sc.Sks[tx * 4 + 2];
            o4.w = acc[rn][3] + sq + sm.sc.Sks[tx * 4 + 3];
            *(float4*)&out_score[n * NN + m0 + tx * 4] = o4;
        }
    }
    gsync();

    // ===== S6: softmax (warp per row), in place =====
    if (vb < 96) {
        int row = vb * 8 + (tid >> 5);
        int lane = tid & 31;
        float* p = out_score + row * NN;
        float v[24];
        float mx = -1e30f;
        #pragma unroll
        for (int i = 0; i < 24; i++) { v[i] = p[lane + i * 32]; mx = fmaxf(mx, v[i]); }
        #pragma unroll
        for (int o = 16; o; o >>= 1) mx = fmaxf(mx, __shfl_xor_sync(0xffffffffu, mx, o));
        float s = 0.f;
        #pragma unroll
        for (int i = 0; i < 24; i++) { v[i] = __expf(v[i] - mx); s += v[i]; }
        #pragma unroll
        for (int o = 16; o; o >>= 1) s += __shfl_xor_sync(0xffffffffu, s, o);
        float inv = 1.f / s;
        #pragma unroll
        for (int i = 0; i < 24; i++) p[lane + i * 32] = v[i] * inv;
    }
    gsync();

    // ===== S7: av partials (48 n-tiles x 4 k-splits) =====
    if (vb < 192) {
        int nt = vb % 48, ks = vb / 48;
        int n0 = nt * 16;
        int d0  = (tid & 31) * 2;
        int nl0 = (tid >> 5) * 2;
        float a00 = 0.f, a01 = 0.f, a10 = 0.f, a11 = 0.f;
        for (int c = 0; c < 3; c++) {
            int mb = ks * 192 + c * 64;
            for (int idx = tid; idx < 64 * 64; idx += 256)
                sm.av.Vs[idx] = g_vT[(mb + (idx >> 6)) * 64 + (idx & 63)];
            for (int idx = tid; idx < 16 * 64; idx += 256)
                sm.av.Ps[idx] = out_score[(n0 + (idx >> 6)) * NN + mb + (idx & 63)];
            __syncthreads();
            #pragma unroll 4
            for (int m = 0; m < 64; m++) {
                float2 vv = *(const float2*)&sm.av.Vs[m * 64 + d0];
                float p0 = sm.av.Ps[nl0 * 64 + m], p1 = sm.av.Ps[(nl0 + 1) * 64 + m];
                a00 = fmaf(p0, vv.x, a00); a01 = fmaf(p0, vv.y, a01);
                a10 = fmaf(p1, vv.x, a10); a11 = fmaf(p1, vv.y, a11);
            }
            __syncthreads();
        }
        float* dst = g_avp + ks * (64 * NN);
        dst[d0 * NN + n0 + nl0]           = a00;
        dst[(d0 + 1) * NN + n0 + nl0]     = a01;
        dst[d0 * NN + n0 + nl0 + 1]       = a10;
        dst[(d0 + 1) * NN + n0 + nl0 + 1] = a11;
    }
    gsync();

    // ===== S8: g1 = cw1[:,:64]@desc1 + W'@av(sum 4 partials) + b' =====
    if (vb < 96) {
        int o0 = (vb / 6) * 8, c0 = (vb % 6) * 128;
        float acc[4] = {};
        fillW8(sm.g.wT, cw1, 128, o0, 0);
        __syncthreads();
        gemm8p(desc1, c0, sm.g.wT, acc);
        __syncthreads();
        fillW8(sm.g.wT, g_Wp, 64, o0, 0);
        __syncthreads();
        gemm8s4(g_avp, c0, sm.g.wT, acc);
        int c = tid & 127, rg = tid >> 7;
        int ob = o0 + rg * 4;
        #pragma unroll
        for (int r = 0; r < 4; r++)
            g_g1[(ob + r) * NN + c0 + c] = acc[r] + g_bp[ob + r];
    }
    gsync();

    // ===== S9: bnorm1d coefficients =====
    if (vb < 128) {
        float s = 0.f, s2 = 0.f;
        #pragma unroll
        for (int j = 0; j < 3; j++) {
            float x = g_g1[vb * NN + tid + j * 256];
            s += x; s2 += x * x;
        }
        s = bsum256(s, sm.st.r1); s2 = bsum256(s2, sm.st.r2);
        if (tid == 0) {
            float m = s * (1.f / NN);
            float v = s2 * (1.f / NN) - m * m;
            float scale = rsqrtf(v + 1e-5f) * cbg[vb];
            g_ncc[vb] = make_float2(scale, -m * scale + cbb[vb]);
        }
    }
    gsync();

    // ===== S10: out_desc = desc1 + cw2 @ relu(norm(g1)) + cb2 =====
    if (vb < 48) {
        int o0 = (vb / 6) * 8, c0 = (vb % 6) * 128;
        float acc[4] = {};
        if (tid < 64) sm.g.nb[tid] = g_ncc[tid];
        fillW8(sm.g.wT, cw2, 128, o0, 0);
        __syncthreads();
        gemm8n(g_g1, c0, sm.g.wT, sm.g.nb, acc);
        __syncthreads();
        if (tid < 64) sm.g.nb[tid] = g_ncc[64 + tid];
        fillW8(sm.g.wT, cw2, 128, o0, 64);
        __syncthreads();
        gemm8n(g_g1 + 64 * NN, c0, sm.g.wT, sm.g.nb, acc);
        int c = tid & 127, rg = tid >> 7;
        int ob = o0 + rg * 4;
        #pragma unroll
        for (int r = 0; r < 4; r++)
            out_desc[(ob + r) * NN + c0 + c] =
                acc[r] + cb2[ob + r] + desc1[(ob + r) * NN + c0 + c];
    }
}

// ---------------- launch ----------------
extern "C" void kernel_launch(void* const* d_in, const int* in_sizes, int n_in,
                              void* d_out, int out_size)
{
    const float* desc1 = (const float*)d_in[0];
    const float* desc2 = (const float*)d_in[1];
    const float* qw  = (const float*)d_in[2];  const float* qb  = (const float*)d_in[3];
    const float* kw  = (const float*)d_in[4];  const float* kb  = (const float*)d_in[5];
    const float* vw  = (const float*)d_in[6];  const float* vb  = (const float*)d_in[7];
    const float* mhw = (const float*)d_in[8];  const float* mhb = (const float*)d_in[9];
    const float* cw1 = (const float*)d_in[10]; const float* cb1 = (const float*)d_in[11];
    const float* cbg = (const float*)d_in[12]; const float* cbb = (const float*)d_in[13];
    const float* cw2 = (const float*)d_in[14]; const float* cb2 = (const float*)d_in[15];
    const float* shw = (const float*)d_in[16]; const float* shb = (const float*)d_in[17];
    const float* bn1g = (const float*)d_in[18]; const float* bn1b = (const float*)d_in[19];
    const float* sw1 = (const float*)d_in[20]; const float* sb1 = (const float*)d_in[21];
    const float* bn2g = (const float*)d_in[22]; const float* bn2b = (const float*)d_in[23];
    const float* sw2 = (const float*)d_in[24]; const float* sb2 = (const float*)d_in[25];

    float* out = (float*)d_out;
    float* out_desc  = out;
    float* out_score = out + 64 * NN;

    k_fused<<<512, 256>>>(desc1, desc2, qw, qb, kw, kb, vw, vb, mhw, mhb,
                          cw1, cb1, cbg, cbb, cw2, cb2, shw, shb,
                          bn1g, bn1b, sw1, sb1, bn2g, bn2b, sw2, sb2,
                          out_desc, out_score);
}